// round 15
// baseline (speedup 1.0000x reference)
#include <cuda_runtime.h>
#include <cstdint>

// Weight of packed upper-triangular entry e=(i,j), i<=j, of the 8x8 moment
// matrix M in loss_b = sum_e w_e * M_b[e]^2:
//   both in P-block (0..3): diag 1, off-diag 2   (||PP^T||_F^2)
//   i in P, j in S (4..7):  -2                   (-2||PS^T||_F^2)
//   both in S-block:        diag 1, off-diag 2   (||SS^T||_F^2)
__constant__ float c_w[36] = {
    1.f, 2.f, 2.f, 2.f, -2.f, -2.f, -2.f, -2.f,   // i=0
    1.f, 2.f, 2.f, -2.f, -2.f, -2.f, -2.f,        // i=1
    1.f, 2.f, -2.f, -2.f, -2.f, -2.f,             // i=2
    1.f, -2.f, -2.f, -2.f, -2.f,                  // i=3
    1.f, 2.f, 2.f, 2.f,                           // i=4
    1.f, 2.f, 2.f,                                // i=5
    1.f, 2.f,                                     // i=6
    1.f                                           // i=7
};

__device__ __forceinline__ uint32_t smem_u32(const void* p)
{
    uint32_t a;
    asm("{ .reg .u64 t; cvta.to.shared.u64 t, %1; cvt.u32.u64 %0, t; }"
        : "=r"(a) : "l"(p));
    return a;
}

// Map a local smem address to the same offset in cluster rank 0's smem.
__device__ __forceinline__ uint32_t mapa_rank0(uint32_t local_addr)
{
    uint32_t r;
    asm("mapa.shared::cluster.u32 %0, %1, 0;" : "=r"(r) : "r"(local_addr));
    return r;
}

// One cluster of 8 CTAs x 512 threads. CTA blk: batch b = blk>>1,
// half = blk&1 of the 4096 spatial positions. Each thread owns one float4
// group (4 positions). v_n = [p_n/||p_n||, s_n/||s_n||] in R^8; each CTA
// accumulates the 36 unique entries of sum_n v_n v_n^T for its slice.
// Warps 0+1 publish the 36 column sums straight into rank 0's smem via
// DSMEM (one entry per lane) and arrive on rank 0's mbarrier (16 arrivals).
// Rank 0 waits and evaluates
//   loss = sum_b (||PP^T||^2 - 2||PS^T||^2 + ||SS^T||^2) / (B*N*N)
// via the exact identity sum_nm (a_n.a_m)(b_n.b_m) = ||A B^T||_F^2.
// Loads issue before any barrier; the split cluster barrier (release-arrive
// early, wait after local compute) hides barrier latency under real work.
__global__ void __launch_bounds__(512, 1) __cluster_dims__(8, 1, 1)
cosine_ssm_cluster_kernel(const float* __restrict__ xp,
                          const float* __restrict__ xs,
                          float* __restrict__ out)
{
    constexpr int N = 4096;
    __shared__ float red[64][37];   // stride 37 -> conflict-free columns
    __shared__ float part[36][9];   // [entry][rank], 9-pad
    __shared__ __align__(16) float fin[32];
    __shared__ __align__(8) unsigned long long mbar;

    const int blk  = blockIdx.x;
    const int b    = blk >> 1;      // batch (2 CTAs per batch)
    const int half = blk & 1;       // half of the spatial dim
    const int t    = threadIdx.x;
    const int warp = t >> 5;
    const int lane = t & 31;

    uint32_t rank;
    asm("mov.u32 %0, %%cluster_ctarank;" : "=r"(rank));

    // Issue all global loads FIRST: the DRAM miss starts immediately and
    // the mbarrier init + barriers below execute under it.
    const float* pb = xp + b * 4 * N;
    const float* sb = xs + b * 4 * N;
    const int g = half * 2048 + t * 4;   // starting spatial index

    float pv[4][4], sv[4][4];
#pragma unroll
    for (int c = 0; c < 4; ++c) {
        float4 a = *reinterpret_cast<const float4*>(pb + c * N + g);
        pv[c][0] = a.x; pv[c][1] = a.y; pv[c][2] = a.z; pv[c][3] = a.w;
        float4 q = *reinterpret_cast<const float4*>(sb + c * N + g);
        sv[c][0] = q.x; sv[c][1] = q.y; sv[c][2] = q.z; sv[c][3] = q.w;
    }

    const uint32_t mbar_addr = smem_u32(&mbar);
    if (t == 0)
        asm volatile("mbarrier.init.shared.b64 [%0], 16;"
                     :: "r"(mbar_addr) : "memory");
    __syncthreads();   // init visible CTA-wide before this CTA's arrive

    // Split barrier, part 1 (RELEASE arrive: publishes the mbarrier init to
    // the cluster so no remote arrive can race it). Non-blocking; its cost
    // is hidden under the in-flight loads.
    asm volatile("barrier.cluster.arrive.aligned;" ::: "memory");

    float acc[36];
#pragma unroll
    for (int i = 0; i < 36; ++i) acc[i] = 0.0f;

#pragma unroll
    for (int k = 0; k < 4; ++k) {
        float sumsq_p = pv[0][k] * pv[0][k] + pv[1][k] * pv[1][k]
                      + pv[2][k] * pv[2][k] + pv[3][k] * pv[3][k];
        float sumsq_s = sv[0][k] * sv[0][k] + sv[1][k] * sv[1][k]
                      + sv[2][k] * sv[2][k] + sv[3][k] * sv[3][k];
        // x / max(||x||, 1e-12)  ==  x * rsqrt(max(||x||^2, 1e-24))
        float ip = rsqrtf(fmaxf(sumsq_p, 1e-24f));
        float is = rsqrtf(fmaxf(sumsq_s, 1e-24f));
        float v[8];
#pragma unroll
        for (int c = 0; c < 4; ++c) {
            v[c]     = pv[c][k] * ip;
            v[4 + c] = sv[c][k] * is;
        }
        int idx = 0;
#pragma unroll
        for (int i = 0; i < 8; ++i)
#pragma unroll
            for (int jj = i; jj < 8; ++jj)
                acc[idx++] += v[i] * v[jj];
    }

    // 3 butterfly rounds: lanes 0..3 hold sums of lanes {l, l+4, ..., l+28}.
#pragma unroll
    for (int off = 16; off >= 4; off >>= 1)
#pragma unroll
        for (int i = 0; i < 36; ++i)
            acc[i] += __shfl_down_sync(0xffffffffu, acc[i], off);

    if (lane < 4) {
        float* row = red[warp * 4 + lane];   // 16 warps x 4 = 64 rows
#pragma unroll
        for (int i = 0; i < 36; ++i) row[i] = acc[i];
    }
    __syncthreads();

    // Split barrier, part 2: every CTA arrived ~1000+ cycles ago, so this
    // completes on the fast path. Acquire pairs with the release-arrives:
    // all CTAs' mbarrier inits are visible before any remote arrive below.
    asm volatile("barrier.cluster.wait.acquire.aligned;" ::: "memory");

    if (warp >= 2) return;

    // ---- warps 0+1: column sums, one entry per lane, direct DSMEM publish.
    // warp 0 -> entries 0..31, warp 1 lanes 0..3 -> entries 32..35.
    const int col = warp * 32 + lane;
    if (col < 36) {
        float v[8];
#pragma unroll
        for (int j = 0; j < 8; ++j) v[j] = red[j][col];
#pragma unroll
        for (int r = 8; r < 64; r += 8)
#pragma unroll
            for (int j = 0; j < 8; ++j) v[j] += red[r + j][col];
        float s = ((v[0] + v[1]) + (v[2] + v[3]))
                + ((v[4] + v[5]) + (v[6] + v[7]));
        uint32_t raddr = mapa_rank0(smem_u32(&part[col][rank]));
        asm volatile("st.shared::cluster.f32 [%0], %1;"
                     :: "r"(raddr), "f"(s) : "memory");
    }
    __syncwarp();
    if (lane == 0) {
        // Release-arrive on rank 0's mbarrier (orders this warp's DSMEM
        // stores; __syncwarp chains the other lanes' stores into it).
        uint32_t rmbar = mapa_rank0(mbar_addr);
        asm volatile("mbarrier.arrive.shared::cluster.b64 _, [%0];"
                     :: "r"(rmbar) : "memory");
    }
    if (rank != 0 || warp != 0) return;

    // ---- rank 0, warp 0: wait for all 16 arrivals (acquire.cluster) ----
    asm volatile(
        "{\n\t"
        ".reg .pred P;\n\t"
        "W_%=:\n\t"
        "mbarrier.try_wait.parity.acquire.cluster.shared::cta.b64 P, [%0], 0;\n\t"
        "@!P bra W_%=;\n\t"
        "}"
        :: "r"(mbar_addr) : "memory");

    // lane l handles entry l; lanes 0..3 also entries 32..35.
    // Batch b's two CTA partials are columns {2b, 2b+1}.
    float val;
    {
        const float* r = part[lane];
        float m0 = r[0] + r[1], m1 = r[2] + r[3];
        float m2 = r[4] + r[5], m3 = r[6] + r[7];
        val = c_w[lane] * ((m0 * m0 + m1 * m1) + (m2 * m2 + m3 * m3));
    }
    if (lane < 4) {
        const float* r = part[32 + lane];
        float m0 = r[0] + r[1], m1 = r[2] + r[3];
        float m2 = r[4] + r[5], m3 = r[6] + r[7];
        val += c_w[32 + lane] * ((m0 * m0 + m1 * m1) + (m2 * m2 + m3 * m3));
    }

    // Final reduce via smem (8 independent LDS.128 + depth-5 tree) instead
    // of a 5-round dependent shuffle chain.
    fin[lane] = val;
    __syncwarp();
    if (lane == 0) {
        const float4* f = reinterpret_cast<const float4*>(fin);
        float4 a = f[0], bq = f[1], cq = f[2], dq = f[3];
        float4 e = f[4], h = f[5], i = f[6], j = f[7];
        float s0 = ((a.x + a.y) + (a.z + a.w)) + ((bq.x + bq.y) + (bq.z + bq.w));
        float s1 = ((cq.x + cq.y) + (cq.z + cq.w)) + ((dq.x + dq.y) + (dq.z + dq.w));
        float s2 = ((e.x + e.y) + (e.z + e.w)) + ((h.x + h.y) + (h.z + h.w));
        float s3 = ((i.x + i.y) + (i.z + i.w)) + ((j.x + j.y) + (j.z + j.w));
        out[0] = ((s0 + s1) + (s2 + s3)) * (1.0f / (4.0f * 4096.0f * 4096.0f));
    }
}

extern "C" void kernel_launch(void* const* d_in, const int* in_sizes, int n_in,
                              void* d_out, int out_size)
{
    const float* xp = (const float*)d_in[0];  // x_pred [4,4,64,64] fp32
    const float* xs = (const float*)d_in[1];  // x_src  [4,4,64,64] fp32
    cosine_ssm_cluster_kernel<<<8, 512>>>(xp, xs, (float*)d_out);
}

// round 16
// speedup vs baseline: 1.0295x; 1.0295x over previous
#include <cuda_runtime.h>
#include <cstdint>

// Weight of packed upper-triangular entry e=(i,j), i<=j, of the 8x8 moment
// matrix M in loss_b = sum_e w_e * M_b[e]^2:
//   both in P-block (0..3): diag 1, off-diag 2   (||PP^T||_F^2)
//   i in P, j in S (4..7):  -2                   (-2||PS^T||_F^2)
//   both in S-block:        diag 1, off-diag 2   (||SS^T||_F^2)
__constant__ float c_w[36] = {
    1.f, 2.f, 2.f, 2.f, -2.f, -2.f, -2.f, -2.f,   // i=0
    1.f, 2.f, 2.f, -2.f, -2.f, -2.f, -2.f,        // i=1
    1.f, 2.f, -2.f, -2.f, -2.f, -2.f,             // i=2
    1.f, -2.f, -2.f, -2.f, -2.f,                  // i=3
    1.f, 2.f, 2.f, 2.f,                           // i=4
    1.f, 2.f, 2.f,                                // i=5
    1.f, 2.f,                                     // i=6
    1.f                                           // i=7
};

__device__ __forceinline__ uint32_t smem_u32(const void* p)
{
    uint32_t a;
    asm("{ .reg .u64 t; cvta.to.shared.u64 t, %1; cvt.u32.u64 %0, t; }"
        : "=r"(a) : "l"(p));
    return a;
}

// Map a local smem address to the same offset in cluster rank 0's smem.
__device__ __forceinline__ uint32_t mapa_rank0(uint32_t local_addr)
{
    uint32_t r;
    asm("mapa.shared::cluster.u32 %0, %1, 0;" : "=r"(r) : "r"(local_addr));
    return r;
}

// One cluster of 8 CTAs x 512 threads. CTA blk: batch b = blk>>1,
// half = blk&1 of the 4096 spatial positions. Each thread owns one float4
// group (4 positions). v_n = [p_n/||p_n||, s_n/||s_n||] in R^8; each CTA
// accumulates the 36 unique entries of sum_n v_n v_n^T for its slice.
// Warps 0+1 publish the 36 column sums straight into rank 0's smem via
// DSMEM (one entry per lane) and arrive on rank 0's mbarrier (16 arrivals).
// Rank 0 waits and evaluates
//   loss = sum_b (||PP^T||^2 - 2||PS^T||^2 + ||SS^T||^2) / (B*N*N)
// via the exact identity sum_nm (a_n.a_m)(b_n.b_m) = ||A B^T||_F^2.
// Split cluster barrier: RELEASE-arrive immediately after mbarrier init
// (no in-flight memory ops -> fence is ~free, and it publishes the init to
// the cluster), wait only after all local compute (fast path by then).
__global__ void __launch_bounds__(512, 1) __cluster_dims__(8, 1, 1)
cosine_ssm_cluster_kernel(const float* __restrict__ xp,
                          const float* __restrict__ xs,
                          float* __restrict__ out)
{
    constexpr int N = 4096;
    __shared__ float red[64][37];   // stride 37 -> conflict-free columns
    __shared__ float part[36][9];   // [entry][rank], 9-pad
    __shared__ __align__(16) float fin[32];
    __shared__ __align__(8) unsigned long long mbar;

    const int blk  = blockIdx.x;
    const int b    = blk >> 1;      // batch (2 CTAs per batch)
    const int half = blk & 1;       // half of the spatial dim
    const int t    = threadIdx.x;
    const int warp = t >> 5;
    const int lane = t & 31;

    uint32_t rank;
    asm("mov.u32 %0, %%cluster_ctarank;" : "=r"(rank));

    const uint32_t mbar_addr = smem_u32(&mbar);
    if (t == 0)
        asm volatile("mbarrier.init.shared.b64 [%0], 16;"
                     :: "r"(mbar_addr) : "memory");
    __syncthreads();   // init visible CTA-wide before this CTA's arrive

    // Split barrier, part 1: RELEASE arrive (publishes the mbarrier init to
    // the cluster; no remote mbarrier.arrive can race it). Non-blocking,
    // and with no loads yet in flight the release fence is nearly free.
    asm volatile("barrier.cluster.arrive.aligned;" ::: "memory");

    const float* pb = xp + b * 4 * N;
    const float* sb = xs + b * 4 * N;
    const int g = half * 2048 + t * 4;   // starting spatial index

    float pv[4][4], sv[4][4];
#pragma unroll
    for (int c = 0; c < 4; ++c) {
        float4 a = *reinterpret_cast<const float4*>(pb + c * N + g);
        pv[c][0] = a.x; pv[c][1] = a.y; pv[c][2] = a.z; pv[c][3] = a.w;
        float4 q = *reinterpret_cast<const float4*>(sb + c * N + g);
        sv[c][0] = q.x; sv[c][1] = q.y; sv[c][2] = q.z; sv[c][3] = q.w;
    }

    float acc[36];
#pragma unroll
    for (int i = 0; i < 36; ++i) acc[i] = 0.0f;

#pragma unroll
    for (int k = 0; k < 4; ++k) {
        float sumsq_p = pv[0][k] * pv[0][k] + pv[1][k] * pv[1][k]
                      + pv[2][k] * pv[2][k] + pv[3][k] * pv[3][k];
        float sumsq_s = sv[0][k] * sv[0][k] + sv[1][k] * sv[1][k]
                      + sv[2][k] * sv[2][k] + sv[3][k] * sv[3][k];
        // x / max(||x||, 1e-12)  ==  x * rsqrt(max(||x||^2, 1e-24))
        float ip = rsqrtf(fmaxf(sumsq_p, 1e-24f));
        float is = rsqrtf(fmaxf(sumsq_s, 1e-24f));
        float v[8];
#pragma unroll
        for (int c = 0; c < 4; ++c) {
            v[c]     = pv[c][k] * ip;
            v[4 + c] = sv[c][k] * is;
        }
        int idx = 0;
#pragma unroll
        for (int i = 0; i < 8; ++i)
#pragma unroll
            for (int jj = i; jj < 8; ++jj)
                acc[idx++] += v[i] * v[jj];
    }

    // 3 butterfly rounds: lanes 0..3 hold sums of lanes {l, l+4, ..., l+28}.
#pragma unroll
    for (int off = 16; off >= 4; off >>= 1)
#pragma unroll
        for (int i = 0; i < 36; ++i)
            acc[i] += __shfl_down_sync(0xffffffffu, acc[i], off);

    if (lane < 4) {
        float* row = red[warp * 4 + lane];   // 16 warps x 4 = 64 rows
#pragma unroll
        for (int i = 0; i < 36; ++i) row[i] = acc[i];
    }
    __syncthreads();

    // Split barrier, part 2: every CTA arrived ~1000+ cycles ago, so this
    // completes on the fast path. Acquire pairs with the release-arrives:
    // all CTAs' mbarrier inits are visible before any remote arrive below.
    asm volatile("barrier.cluster.wait.acquire.aligned;" ::: "memory");

    if (warp >= 2) return;

    // ---- warps 0+1: column sums, one entry per lane, direct DSMEM publish.
    // warp 0 -> entries 0..31, warp 1 lanes 0..3 -> entries 32..35.
    const int col = warp * 32 + lane;
    if (col < 36) {
        float v[8];
#pragma unroll
        for (int j = 0; j < 8; ++j) v[j] = red[j][col];
#pragma unroll
        for (int r = 8; r < 64; r += 8)
#pragma unroll
            for (int j = 0; j < 8; ++j) v[j] += red[r + j][col];
        float s = ((v[0] + v[1]) + (v[2] + v[3]))
                + ((v[4] + v[5]) + (v[6] + v[7]));
        uint32_t raddr = mapa_rank0(smem_u32(&part[col][rank]));
        asm volatile("st.shared::cluster.f32 [%0], %1;"
                     :: "r"(raddr), "f"(s) : "memory");
    }
    __syncwarp();
    if (lane == 0) {
        // Release-arrive on rank 0's mbarrier (orders this warp's DSMEM
        // stores; __syncwarp chains the other lanes' stores into it).
        uint32_t rmbar = mapa_rank0(mbar_addr);
        asm volatile("mbarrier.arrive.shared::cluster.b64 _, [%0];"
                     :: "r"(rmbar) : "memory");
    }
    if (rank != 0 || warp != 0) return;

    // ---- rank 0, warp 0: wait for all 16 arrivals (acquire.cluster) ----
    asm volatile(
        "{\n\t"
        ".reg .pred P;\n\t"
        "W_%=:\n\t"
        "mbarrier.try_wait.parity.acquire.cluster.shared::cta.b64 P, [%0], 0;\n\t"
        "@!P bra W_%=;\n\t"
        "}"
        :: "r"(mbar_addr) : "memory");

    // lane l handles entry l; lanes 0..3 also entries 32..35.
    // Batch b's two CTA partials are columns {2b, 2b+1}.
    float val;
    {
        const float* r = part[lane];
        float m0 = r[0] + r[1], m1 = r[2] + r[3];
        float m2 = r[4] + r[5], m3 = r[6] + r[7];
        val = c_w[lane] * ((m0 * m0 + m1 * m1) + (m2 * m2 + m3 * m3));
    }
    if (lane < 4) {
        const float* r = part[32 + lane];
        float m0 = r[0] + r[1], m1 = r[2] + r[3];
        float m2 = r[4] + r[5], m3 = r[6] + r[7];
        val += c_w[32 + lane] * ((m0 * m0 + m1 * m1) + (m2 * m2 + m3 * m3));
    }

    // Final reduce via smem (8 independent LDS.128 + depth-5 tree) instead
    // of a 5-round dependent shuffle chain.
    fin[lane] = val;
    __syncwarp();
    if (lane == 0) {
        const float4* f = reinterpret_cast<const float4*>(fin);
        float4 a = f[0], bq = f[1], cq = f[2], dq = f[3];
        float4 e = f[4], h = f[5], i = f[6], j = f[7];
        float s0 = ((a.x + a.y) + (a.z + a.w)) + ((bq.x + bq.y) + (bq.z + bq.w));
        float s1 = ((cq.x + cq.y) + (cq.z + cq.w)) + ((dq.x + dq.y) + (dq.z + dq.w));
        float s2 = ((e.x + e.y) + (e.z + e.w)) + ((h.x + h.y) + (h.z + h.w));
        float s3 = ((i.x + i.y) + (i.z + i.w)) + ((j.x + j.y) + (j.z + j.w));
        out[0] = ((s0 + s1) + (s2 + s3)) * (1.0f / (4.0f * 4096.0f * 4096.0f));
    }
}

extern "C" void kernel_launch(void* const* d_in, const int* in_sizes, int n_in,
                              void* d_out, int out_size)
{
    const float* xp = (const float*)d_in[0];  // x_pred [4,4,64,64] fp32
    const float* xs = (const float*)d_in[1];  // x_src  [4,4,64,64] fp32
    cosine_ssm_cluster_kernel<<<8, 512>>>(xp, xs, (float*)d_out);
}